// round 2
// baseline (speedup 1.0000x reference)
#include <cuda_runtime.h>
#include <cuda_bf16.h>
#include <cstdint>

// Problem constants
#define NB   4
#define TT   1024
#define VV   32000
#define HH   512
#define MROWS (NB*TT)            // 4096
#define YSIZE ((size_t)MROWS*VV) // 131072000

// Scratch (allocation-free rule -> __device__ globals)
__device__ float g_xh[2u*TT*NB*HH];     // [dir][s][n][j] 16 MB (backward pre-reversed in time)
__device__ float g_z[(size_t)MROWS*2*HH]; // [m][k] A-matrix for output GEMM, 16 MB

// ---------------------------------------------------------------------------
// Kernel 1: embedding gather.  xh[dir][s][n][:] = embed_dir[ x[n][ t(dir,s) ] ]
// ---------------------------------------------------------------------------
__global__ __launch_bounds__(128)
void gather_kernel(const int* __restrict__ x,
                   const float* __restrict__ Ef,
                   const float* __restrict__ Eb)
{
    int b   = blockIdx.x;          // 0..8191
    int dir = b >> 12;
    int s   = (b >> 2) & 1023;
    int n   = b & 3;
    int t   = dir ? (TT - 1 - s) : s;
    int tok = x[n * TT + t];
    const float4* src = (const float4*)((dir ? Eb : Ef) + (size_t)tok * HH);
    float4* dst = (float4*)(g_xh + ((size_t)(dir * TT + s) * NB + n) * HH);
    dst[threadIdx.x] = src[threadIdx.x];   // 128 threads x float4 = 512 floats
}

// ---------------------------------------------------------------------------
// Kernel 2: bidirectional RNN scan.
// grid = 16 CTAs, cluster of 8 per direction. 256 threads/CTA.
// Thread (ks = tid>>6, jj = tid&63): holds Wh[ks*128 .. ks*128+127][j] in regs,
// computes K-slice partials for all 4 batch rows of column j = rank*64+jj.
// Phase 2: thread acts as (n = ks, j): reduces 4 K-slices, tanh, writes z,
// broadcasts h_new to all 8 CTAs via DSMEM, then barrier.cluster.
// ---------------------------------------------------------------------------
__device__ __forceinline__ unsigned smem_u32(const void* p)
{
    unsigned a;
    asm("{ .reg .u64 t; cvta.to.shared.u64 t, %1; cvt.u32.u64 %0, t; }"
        : "=r"(a) : "l"(p));
    return a;
}

__global__ __cluster_dims__(8, 1, 1) __launch_bounds__(256, 1)
void rnn_kernel(const float* __restrict__ Wh_f, const float* __restrict__ Wh_b,
                const float* __restrict__ bh_f, const float* __restrict__ bh_b,
                float* __restrict__ out)
{
    __shared__ float h_s[2][HH][NB];   // [buf][i][n], 16 KB
    __shared__ float red[4][NB][64];   // [kslice][n][jj], 4 KB

    int tid = threadIdx.x;
    int jj  = tid & 63;
    int ks  = tid >> 6;
    unsigned crank;
    asm("mov.u32 %0, %%cluster_ctarank;" : "=r"(crank));
    int dir = blockIdx.x >> 3;
    int j   = (int)crank * 64 + jj;

    const float* Wh = dir ? Wh_b : Wh_f;
    const float* bh = dir ? bh_b : bh_f;

    // Persistent register-resident weight slice: Wh[ks*128+u][j]
    float wreg[128];
#pragma unroll
    for (int u = 0; u < 128; ++u)
        wreg[u] = Wh[(size_t)(ks * 128 + u) * HH + j];
    float bhv = bh[j];

    // h0 = 0
    for (int i = tid; i < HH * NB; i += 256) ((float*)h_s[0])[i] = 0.f;
    __syncthreads();
    asm volatile("barrier.cluster.arrive.aligned;" ::: "memory");
    asm volatile("barrier.cluster.wait.aligned;"   ::: "memory");

    const float* xh_base = g_xh + (size_t)dir * TT * NB * HH;
    int p = 0;

    for (int s = 0; s < TT; ++s) {
        // prefetch the xh value consumed in phase 2 (role: n = ks)
        float xv = xh_base[((size_t)s * NB + ks) * HH + j];

        // phase 1: partial dot over i in [ks*128, ks*128+128) for 4 batch rows
        float a0 = 0.f, a1 = 0.f, a2 = 0.f, a3 = 0.f;
        const float4* hp = (const float4*)(&h_s[p][ks * 128][0]);
#pragma unroll
        for (int u = 0; u < 128; ++u) {
            float4 hv = hp[u];
            float  w  = wreg[u];
            a0 = fmaf(hv.x, w, a0);
            a1 = fmaf(hv.y, w, a1);
            a2 = fmaf(hv.z, w, a2);
            a3 = fmaf(hv.w, w, a3);
        }
        red[ks][0][jj] = a0;
        red[ks][1][jj] = a1;
        red[ks][2][jj] = a2;
        red[ks][3][jj] = a3;
        __syncthreads();

        // phase 2: thread = (n = ks, j)
        float v = red[0][ks][jj] + red[1][ks][jj] + red[2][ks][jj] + red[3][ks][jj]
                + xv + bhv;
        float hn = tanhf(v);

        int t_out = dir ? (TT - 1 - s) : s;
        g_z[((size_t)ks * TT + t_out) * (2 * HH) + dir * HH + j] = hn;
        if (s == TT - 1)
            out[YSIZE + (size_t)dir * (NB * HH) + ks * HH + j] = hn;

        // broadcast h_new[n=ks][j] into every CTA's h_s[1-p][j][ks]
        unsigned laddr = smem_u32(&h_s[1 - p][j][ks]);
#pragma unroll
        for (int c = 0; c < 8; ++c) {
            unsigned raddr;
            asm volatile("mapa.shared::cluster.u32 %0, %1, %2;"
                         : "=r"(raddr) : "r"(laddr), "r"(c));
            asm volatile("st.shared::cluster.f32 [%0], %1;"
                         :: "r"(raddr), "f"(hn) : "memory");
        }

        asm volatile("barrier.cluster.arrive.aligned;" ::: "memory");
        asm volatile("barrier.cluster.wait.aligned;"   ::: "memory");
        p ^= 1;
    }
}

// ---------------------------------------------------------------------------
// Kernel 3: logits = z @ Wout + bout   (fp32 SIMT tiled GEMM)
// A = g_z [4096][1024], B = Wout [1024][32000], C = d_out [4096][32000]
// Tile 128x128x16, 256 threads, 8x8 per-thread microtile, double-buffered SMEM.
// ---------------------------------------------------------------------------
__global__ __launch_bounds__(256, 2)
void gemm_kernel(const float* __restrict__ B,
                 const float* __restrict__ bias,
                 float* __restrict__ C)
{
    __shared__ float As[2][16][128];   // [k][m] (A stored transposed)
    __shared__ float Bs[2][16][128];   // [k][v]

    int tid = threadIdx.x;
    int v0  = blockIdx.x * 128;   // 0..249
    int m0  = blockIdx.y * 128;   // 0..31
    int tx  = tid & 15;
    int ty  = tid >> 4;

    float acc[8][8];
#pragma unroll
    for (int i = 0; i < 8; ++i)
#pragma unroll
        for (int jx = 0; jx < 8; ++jx) acc[i][jx] = 0.f;

    // per-stage loader indices (512 float4 per tile, 2 per thread)
    int qa0 = tid * 2, qa1 = tid * 2 + 1;

    // prologue: load stage 0
    {
#pragma unroll
        for (int r = 0; r < 2; ++r) {
            int q = tid * 2 + r;
            int row = q >> 2, c4 = q & 3;
            float4 a = *(const float4*)(g_z + (size_t)(m0 + row) * (2 * HH) + c4 * 4);
            As[0][c4 * 4 + 0][row] = a.x;
            As[0][c4 * 4 + 1][row] = a.y;
            As[0][c4 * 4 + 2][row] = a.z;
            As[0][c4 * 4 + 3][row] = a.w;
            int rowb = q >> 5, c4b = q & 31;
            *(float4*)&Bs[0][rowb][c4b * 4] =
                *(const float4*)(B + (size_t)rowb * VV + v0 + c4b * 4);
        }
    }
    __syncthreads();

    int buf = 0;
    for (int kt = 0; kt < 64; ++kt) {
        float4 ra0, ra1, rb0, rb1;
        if (kt < 63) {
            int k0 = (kt + 1) * 16;
            {
                int row = qa0 >> 2, c4 = qa0 & 3;
                ra0 = *(const float4*)(g_z + (size_t)(m0 + row) * (2 * HH) + k0 + c4 * 4);
                int rowb = qa0 >> 5, c4b = qa0 & 31;
                rb0 = *(const float4*)(B + (size_t)(k0 + rowb) * VV + v0 + c4b * 4);
            }
            {
                int row = qa1 >> 2, c4 = qa1 & 3;
                ra1 = *(const float4*)(g_z + (size_t)(m0 + row) * (2 * HH) + k0 + c4 * 4);
                int rowb = qa1 >> 5, c4b = qa1 & 31;
                rb1 = *(const float4*)(B + (size_t)(k0 + rowb) * VV + v0 + c4b * 4);
            }
        }

#pragma unroll
        for (int kk = 0; kk < 16; ++kk) {
            float a[8], b[8];
            *(float4*)(a)     = *(const float4*)&As[buf][kk][ty * 8];
            *(float4*)(a + 4) = *(const float4*)&As[buf][kk][ty * 8 + 4];
            *(float4*)(b)     = *(const float4*)&Bs[buf][kk][tx * 8];
            *(float4*)(b + 4) = *(const float4*)&Bs[buf][kk][tx * 8 + 4];
#pragma unroll
            for (int i = 0; i < 8; ++i)
#pragma unroll
                for (int jx = 0; jx < 8; ++jx)
                    acc[i][jx] = fmaf(a[i], b[jx], acc[i][jx]);
        }

        if (kt < 63) {
            int nb = buf ^ 1;
            {
                int row = qa0 >> 2, c4 = qa0 & 3;
                As[nb][c4 * 4 + 0][row] = ra0.x;
                As[nb][c4 * 4 + 1][row] = ra0.y;
                As[nb][c4 * 4 + 2][row] = ra0.z;
                As[nb][c4 * 4 + 3][row] = ra0.w;
                int rowb = qa0 >> 5, c4b = qa0 & 31;
                *(float4*)&Bs[nb][rowb][c4b * 4] = rb0;
            }
            {
                int row = qa1 >> 2, c4 = qa1 & 3;
                As[nb][c4 * 4 + 0][row] = ra1.x;
                As[nb][c4 * 4 + 1][row] = ra1.y;
                As[nb][c4 * 4 + 2][row] = ra1.z;
                As[nb][c4 * 4 + 3][row] = ra1.w;
                int rowb = qa1 >> 5, c4b = qa1 & 31;
                *(float4*)&Bs[nb][rowb][c4b * 4] = rb1;
            }
        }
        __syncthreads();
        buf ^= 1;
    }

    // epilogue: + bias, store logits
#pragma unroll
    for (int i = 0; i < 8; ++i) {
        size_t base = (size_t)(m0 + ty * 8 + i) * VV + v0 + tx * 8;
#pragma unroll
        for (int jx = 0; jx < 8; ++jx)
            C[base + jx] = acc[i][jx] + bias[v0 + tx * 8 + jx];
    }
}

// ---------------------------------------------------------------------------
// Kernel 4: in-place row softmax over V=32000 (one CTA per row, 256 threads)
// ---------------------------------------------------------------------------
__global__ __launch_bounds__(256, 4)
void softmax_kernel(float* __restrict__ C)
{
    __shared__ float sred[8];
    size_t row = blockIdx.x;
    float* x = C + row * (size_t)VV;
    int tid = threadIdx.x;

    // pass 1: max
    float m = -1e30f;
    for (int i = tid; i < VV; i += 256) m = fmaxf(m, x[i]);
#pragma unroll
    for (int o = 16; o; o >>= 1) m = fmaxf(m, __shfl_xor_sync(0xffffffffu, m, o));
    if ((tid & 31) == 0) sred[tid >> 5] = m;
    __syncthreads();
    float gm = sred[0];
#pragma unroll
    for (int w = 1; w < 8; ++w) gm = fmaxf(gm, sred[w]);
    __syncthreads();

    // pass 2: sum of exp
    float s = 0.f;
    for (int i = tid; i < VV; i += 256) s += __expf(x[i] - gm);
#pragma unroll
    for (int o = 16; o; o >>= 1) s += __shfl_xor_sync(0xffffffffu, s, o);
    if ((tid & 31) == 0) sred[tid >> 5] = s;
    __syncthreads();
    float gs = 0.f;
#pragma unroll
    for (int w = 0; w < 8; ++w) gs += sred[w];
    float inv = 1.0f / gs;

    // pass 3: normalize
    for (int i = tid; i < VV; i += 256) x[i] = __expf(x[i] - gm) * inv;
}

// ---------------------------------------------------------------------------
extern "C" void kernel_launch(void* const* d_in, const int* in_sizes, int n_in,
                              void* d_out, int out_size)
{
    const int*   x       = (const int*)  d_in[0];
    const float* embed_f = (const float*)d_in[1];
    const float* Wh_f    = (const float*)d_in[2];
    const float* bh_f    = (const float*)d_in[3];
    const float* embed_b = (const float*)d_in[4];
    const float* Wh_b    = (const float*)d_in[5];
    const float* bh_b    = (const float*)d_in[6];
    const float* Wout    = (const float*)d_in[7];
    const float* bout    = (const float*)d_in[8];
    float* out = (float*)d_out;

    gather_kernel<<<2 * TT * NB, 128>>>(x, embed_f, embed_b);
    rnn_kernel<<<16, 256>>>(Wh_f, Wh_b, bh_f, bh_b, out);
    dim3 gg(VV / 128, MROWS / 128);
    gemm_kernel<<<gg, 256>>>(Wout, bout, out);
    softmax_kernel<<<MROWS, 256>>>(out);
}

// round 6
// speedup vs baseline: 2.7869x; 2.7869x over previous
#include <cuda_runtime.h>
#include <cuda_bf16.h>
#include <cstdint>

// Problem constants
#define NB   4
#define TT   1024
#define VV   32000
#define HH   512
#define MROWS (NB*TT)            // 4096
#define YSIZE ((size_t)MROWS*VV) // 131072000

// Scratch (allocation-free rule -> __device__ globals)
__device__ float g_xh[2u*TT*NB*HH];       // [dir][s][n][j] 16 MB
__device__ float g_z[(size_t)MROWS*2*HH]; // [m][k] A-matrix for output GEMM, 16 MB
__device__ float g_Wt[(size_t)VV*1024];   // Wout^T [n][k], 128 MB

// ---------------------------------------------------------------------------
// helpers
// ---------------------------------------------------------------------------
__device__ __forceinline__ unsigned smem_u32(const void* p)
{
    unsigned a;
    asm("{ .reg .u64 t; cvta.to.shared.u64 t, %1; cvt.u32.u64 %0, t; }"
        : "=r"(a) : "l"(p));
    return a;
}

__device__ __forceinline__ uint32_t swz(uint32_t o) { return o ^ ((o >> 3) & 0x70); }

__device__ __forceinline__ uint32_t f2tf(uint32_t u)
{
    uint32_t r;
    asm("cvt.rna.tf32.f32 %0, %1;" : "=r"(r) : "f"(__uint_as_float(u)));
    return r;
}

__device__ __forceinline__ void cp16(uint32_t saddr, const void* gaddr)
{
    asm volatile("cp.async.cg.shared.global [%0], [%1], 16;"
                 :: "r"(saddr), "l"(gaddr) : "memory");
}
__device__ __forceinline__ void cp_commit()
{
    asm volatile("cp.async.commit_group;" ::: "memory");
}
__device__ __forceinline__ void cp_wait1()
{
    asm volatile("cp.async.wait_group 1;" ::: "memory");
}
__device__ __forceinline__ void cp_wait0()
{
    asm volatile("cp.async.wait_group 0;" ::: "memory");
}

__device__ __forceinline__ void ldsm4(uint32_t addr, uint32_t& r0, uint32_t& r1,
                                      uint32_t& r2, uint32_t& r3)
{
    asm volatile("ldmatrix.sync.aligned.m8n8.x4.shared.b16 {%0,%1,%2,%3}, [%4];"
                 : "=r"(r0), "=r"(r1), "=r"(r2), "=r"(r3) : "r"(addr));
}

__device__ __forceinline__ void mma8(float* d, const uint32_t* a,
                                     uint32_t b0, uint32_t b1)
{
    asm volatile("mma.sync.aligned.m16n8k8.row.col.f32.tf32.tf32.f32 "
                 "{%0,%1,%2,%3}, {%4,%5,%6,%7}, {%8,%9}, {%0,%1,%2,%3};"
                 : "+f"(d[0]), "+f"(d[1]), "+f"(d[2]), "+f"(d[3])
                 : "r"(a[0]), "r"(a[1]), "r"(a[2]), "r"(a[3]), "r"(b0), "r"(b1));
}

// ---------------------------------------------------------------------------
// Kernel 1: embedding gather
// ---------------------------------------------------------------------------
__global__ __launch_bounds__(128)
void gather_kernel(const int* __restrict__ x,
                   const float* __restrict__ Ef,
                   const float* __restrict__ Eb)
{
    int b   = blockIdx.x;
    int dir = b >> 12;
    int s   = (b >> 2) & 1023;
    int n   = b & 3;
    int t   = dir ? (TT - 1 - s) : s;
    int tok = x[n * TT + t];
    const float4* src = (const float4*)((dir ? Eb : Ef) + (size_t)tok * HH);
    float4* dst = (float4*)(g_xh + ((size_t)(dir * TT + s) * NB + n) * HH);
    dst[threadIdx.x] = src[threadIdx.x];
}

// ---------------------------------------------------------------------------
// Kernel 1b: transpose Wout[k][n] -> g_Wt[n][k]
// ---------------------------------------------------------------------------
__global__ __launch_bounds__(256)
void transpose_kernel(const float* __restrict__ Wout)
{
    __shared__ float t[32][33];
    int n0 = blockIdx.x * 32;
    int k0 = blockIdx.y * 32;
    int tx = threadIdx.x & 31, ty = threadIdx.x >> 5;
#pragma unroll
    for (int r = 0; r < 32; r += 8)
        t[ty + r][tx] = Wout[(size_t)(k0 + ty + r) * VV + n0 + tx];
    __syncthreads();
#pragma unroll
    for (int r = 0; r < 32; r += 8)
        g_Wt[(size_t)(n0 + ty + r) * 1024 + k0 + tx] = t[tx][ty + r];
}

// ---------------------------------------------------------------------------
// Kernel 2: bidirectional RNN scan (cluster-of-8 per direction)
// ---------------------------------------------------------------------------
__global__ __cluster_dims__(8, 1, 1) __launch_bounds__(256, 1)
void rnn_kernel(const float* __restrict__ Wh_f, const float* __restrict__ Wh_b,
                const float* __restrict__ bh_f, const float* __restrict__ bh_b,
                float* __restrict__ out)
{
    __shared__ float h_s[2][HH][NB];
    __shared__ float red[4][NB][64];

    int tid = threadIdx.x;
    int jj  = tid & 63;
    int ks  = tid >> 6;
    unsigned crank;
    asm("mov.u32 %0, %%cluster_ctarank;" : "=r"(crank));
    int dir = blockIdx.x >> 3;
    int j   = (int)crank * 64 + jj;

    const float* Wh = dir ? Wh_b : Wh_f;
    const float* bh = dir ? bh_b : bh_f;

    float wreg[128];
#pragma unroll
    for (int u = 0; u < 128; ++u)
        wreg[u] = Wh[(size_t)(ks * 128 + u) * HH + j];
    float bhv = bh[j];

    for (int i = tid; i < HH * NB; i += 256) ((float*)h_s[0])[i] = 0.f;
    __syncthreads();
    asm volatile("barrier.cluster.arrive.aligned;" ::: "memory");
    asm volatile("barrier.cluster.wait.aligned;"   ::: "memory");

    const float* xh_base = g_xh + (size_t)dir * TT * NB * HH;
    int p = 0;

    for (int s = 0; s < TT; ++s) {
        float xv = xh_base[((size_t)s * NB + ks) * HH + j];

        float a0 = 0.f, a1 = 0.f, a2 = 0.f, a3 = 0.f;
        const float4* hp = (const float4*)(&h_s[p][ks * 128][0]);
#pragma unroll
        for (int u = 0; u < 128; ++u) {
            float4 hv = hp[u];
            float  w  = wreg[u];
            a0 = fmaf(hv.x, w, a0);
            a1 = fmaf(hv.y, w, a1);
            a2 = fmaf(hv.z, w, a2);
            a3 = fmaf(hv.w, w, a3);
        }
        red[ks][0][jj] = a0;
        red[ks][1][jj] = a1;
        red[ks][2][jj] = a2;
        red[ks][3][jj] = a3;
        __syncthreads();

        float v = red[0][ks][jj] + red[1][ks][jj] + red[2][ks][jj] + red[3][ks][jj]
                + xv + bhv;
        float hn = tanhf(v);

        int t_out = dir ? (TT - 1 - s) : s;
        g_z[((size_t)ks * TT + t_out) * (2 * HH) + dir * HH + j] = hn;
        if (s == TT - 1)
            out[YSIZE + (size_t)dir * (NB * HH) + ks * HH + j] = hn;

        unsigned laddr = smem_u32(&h_s[1 - p][j][ks]);
#pragma unroll
        for (int c = 0; c < 8; ++c) {
            unsigned raddr;
            asm volatile("mapa.shared::cluster.u32 %0, %1, %2;"
                         : "=r"(raddr) : "r"(laddr), "r"(c));
            asm volatile("st.shared::cluster.f32 [%0], %1;"
                         :: "r"(raddr), "f"(hn) : "memory");
        }

        asm volatile("barrier.cluster.arrive.aligned;" ::: "memory");
        asm volatile("barrier.cluster.wait.aligned;"   ::: "memory");
        p ^= 1;
    }
}

// ---------------------------------------------------------------------------
// Kernel 3: tf32 mma.sync GEMM  C = g_z(4096x1024) @ g_Wt^T + bias
// CTA tile 128x128x32, 8 warps (2m x 4n), 3-stage cp.async pipeline.
// ---------------------------------------------------------------------------
#define GSMEM (3*32768 + 1024)

__global__ __launch_bounds__(256)
void gemm_kernel(const float* __restrict__ bias, float* __restrict__ C)
{
    extern __shared__ char dsm[];
    uint32_t smbase = (smem_u32(dsm) + 1023) & ~1023u;

    int tid  = threadIdx.x;
    int lane = tid & 31, w = tid >> 5;
    int wm = w >> 2, wn = w & 3;
    int m0 = blockIdx.x * 128, n0 = blockIdx.y * 128;

    // ---- loader constants: 4 A + 4 B float4 copies per thread per chunk ----
    uint32_t sOff[8];
    const float* gP[8];
#pragma unroll
    for (int q = 0; q < 4; ++q) {
        int idx = q * 256 + tid;
        int row = idx >> 3, c4 = idx & 7;
        sOff[q]     = swz((uint32_t)(row * 128 + c4 * 16));
        sOff[q + 4] = 16384u + sOff[q];
        gP[q]     = g_z  + (size_t)(m0 + row) * 1024 + c4 * 4;
        gP[q + 4] = g_Wt + (size_t)(n0 + row) * 1024 + c4 * 4;
    }

    // ---- fragment address constants ----
    int r = lane & 7, g = lane >> 3;
    uint32_t maskv = (uint32_t)r << 4;
    uint32_t hA = (uint32_t)(g >> 1) << 4;
    uint32_t hB = (uint32_t)(g & 1) << 4;
    uint32_t rowA[4], rowB[2];
#pragma unroll
    for (int mf = 0; mf < 4; ++mf)
        rowA[mf] = (uint32_t)((wm * 64 + mf * 16 + (g & 1) * 8 + r) * 128);
#pragma unroll
    for (int nf2 = 0; nf2 < 2; ++nf2)
        rowB[nf2] = 16384u + (uint32_t)((wn * 32 + nf2 * 16 + (g >> 1) * 8 + r) * 128);

    float acc[4][4][4];
#pragma unroll
    for (int i = 0; i < 4; ++i)
#pragma unroll
        for (int jx = 0; jx < 4; ++jx)
#pragma unroll
            for (int e = 0; e < 4; ++e) acc[i][jx][e] = 0.f;

    // ---- prologue: chunks 0,1 ----
#pragma unroll
    for (int q = 0; q < 8; ++q) cp16(smbase + sOff[q], gP[q]);
    cp_commit();
#pragma unroll
    for (int q = 0; q < 8; ++q) cp16(smbase + 32768 + sOff[q], gP[q] + 32);
    cp_commit();

    for (int c = 0; c < 32; ++c) {
        if (c < 31) cp_wait1(); else cp_wait0();
        __syncthreads();

        if (c + 2 < 32) {
            uint32_t sb = smbase + (uint32_t)((c + 2) % 3) * 32768;
            const int ko = (c + 2) * 32;
#pragma unroll
            for (int q = 0; q < 8; ++q) cp16(sb + sOff[q], gP[q] + ko);
            cp_commit();
        }

        uint32_t sb = smbase + (uint32_t)(c % 3) * 32768;
#pragma unroll
        for (int kk = 0; kk < 4; ++kk) {
            uint32_t kof = (uint32_t)kk << 5;
            uint32_t ua[4][4], ub[2][4];
#pragma unroll
            for (int mf = 0; mf < 4; ++mf)
                ldsm4(sb + rowA[mf] + ((kof + hA) ^ maskv),
                      ua[mf][0], ua[mf][1], ua[mf][2], ua[mf][3]);
#pragma unroll
            for (int nf2 = 0; nf2 < 2; ++nf2)
                ldsm4(sb + rowB[nf2] + ((kof + hB) ^ maskv),
                      ub[nf2][0], ub[nf2][1], ub[nf2][2], ub[nf2][3]);
#pragma unroll
            for (int mf = 0; mf < 4; ++mf)
#pragma unroll
                for (int e = 0; e < 4; ++e) ua[mf][e] = f2tf(ua[mf][e]);
#pragma unroll
            for (int nf2 = 0; nf2 < 2; ++nf2)
#pragma unroll
                for (int e = 0; e < 4; ++e) ub[nf2][e] = f2tf(ub[nf2][e]);
#pragma unroll
            for (int mf = 0; mf < 4; ++mf)
#pragma unroll
                for (int nf = 0; nf < 4; ++nf)
                    mma8(acc[mf][nf], ua[mf],
                         ub[nf >> 1][(nf & 1) * 2], ub[nf >> 1][(nf & 1) * 2 + 1]);
        }
        __syncthreads();
    }

    // ---- epilogue: direct STG.64 + bias ----
    float bb0[4], bb1[4];
#pragma unroll
    for (int nf = 0; nf < 4; ++nf) {
        int gcol = n0 + wn * 32 + nf * 8 + 2 * (lane & 3);
        bb0[nf] = bias[gcol];
        bb1[nf] = bias[gcol + 1];
    }
#pragma unroll
    for (int mf = 0; mf < 4; ++mf) {
        int grow = m0 + wm * 64 + mf * 16 + (lane >> 2);
#pragma unroll
        for (int nf = 0; nf < 4; ++nf) {
            int gcol = n0 + wn * 32 + nf * 8 + 2 * (lane & 3);
            float2 v0 = make_float2(acc[mf][nf][0] + bb0[nf], acc[mf][nf][1] + bb1[nf]);
            float2 v1 = make_float2(acc[mf][nf][2] + bb0[nf], acc[mf][nf][3] + bb1[nf]);
            *(float2*)(C + (size_t)grow * VV + gcol)       = v0;
            *(float2*)(C + (size_t)(grow + 8) * VV + gcol) = v1;
        }
    }
}

// ---------------------------------------------------------------------------
// Kernel 4: in-place row softmax (online, 2 passes)
// ---------------------------------------------------------------------------
__global__ __launch_bounds__(256, 4)
void softmax_kernel(float* __restrict__ C)
{
    __shared__ float sm[8], ss[8];
    float* x = C + blockIdx.x * (size_t)VV;
    int tid = threadIdx.x;

    float m = -1e30f, s = 0.f;
    const float4* x4 = (const float4*)x;
    for (int i = tid; i < VV / 4; i += 256) {
        float4 v = x4[i];
        float vm = fmaxf(fmaxf(v.x, v.y), fmaxf(v.z, v.w));
        if (vm > m) { s *= __expf(m - vm); m = vm; }
        s += __expf(v.x - m) + __expf(v.y - m) + __expf(v.z - m) + __expf(v.w - m);
    }
#pragma unroll
    for (int o = 16; o; o >>= 1) {
        float om = __shfl_xor_sync(0xffffffffu, m, o);
        float os = __shfl_xor_sync(0xffffffffu, s, o);
        float nm = fmaxf(m, om);
        s = s * __expf(m - nm) + os * __expf(om - nm);
        m = nm;
    }
    if ((tid & 31) == 0) { sm[tid >> 5] = m; ss[tid >> 5] = s; }
    __syncthreads();
    float M = sm[0];
#pragma unroll
    for (int wq = 1; wq < 8; ++wq) M = fmaxf(M, sm[wq]);
    float S = 0.f;
#pragma unroll
    for (int wq = 0; wq < 8; ++wq) S += ss[wq] * __expf(sm[wq] - M);
    float inv = 1.0f / S;

    float4* xo = (float4*)x;
    for (int i = tid; i < VV / 4; i += 256) {
        float4 v = xo[i];
        v.x = __expf(v.x - M) * inv;
        v.y = __expf(v.y - M) * inv;
        v.z = __expf(v.z - M) * inv;
        v.w = __expf(v.w - M) * inv;
        xo[i] = v;
    }
}

// ---------------------------------------------------------------------------
extern "C" void kernel_launch(void* const* d_in, const int* in_sizes, int n_in,
                              void* d_out, int out_size)
{
    const int*   x       = (const int*)  d_in[0];
    const float* embed_f = (const float*)d_in[1];
    const float* Wh_f    = (const float*)d_in[2];
    const float* bh_f    = (const float*)d_in[3];
    const float* embed_b = (const float*)d_in[4];
    const float* Wh_b    = (const float*)d_in[5];
    const float* bh_b    = (const float*)d_in[6];
    const float* Wout    = (const float*)d_in[7];
    const float* bout    = (const float*)d_in[8];
    float* out = (float*)d_out;

    cudaFuncSetAttribute(gemm_kernel, cudaFuncAttributeMaxDynamicSharedMemorySize,
                         GSMEM);

    gather_kernel<<<2 * TT * NB, 128>>>(x, embed_f, embed_b);
    transpose_kernel<<<dim3(VV / 32, 1024 / 32), 256>>>(Wout);
    rnn_kernel<<<16, 256>>>(Wh_f, Wh_b, bh_f, bh_b, out);
    gemm_kernel<<<dim3(MROWS / 128, VV / 128), 256, GSMEM>>>(bout, out);
    softmax_kernel<<<MROWS, 256>>>(out);
}

// round 7
// speedup vs baseline: 2.9225x; 1.0487x over previous
#include <cuda_runtime.h>
#include <cuda_bf16.h>
#include <cstdint>

// Problem constants
#define NB   4
#define TT   1024
#define VV   32000
#define HH   512
#define MROWS (NB*TT)            // 4096
#define YSIZE ((size_t)MROWS*VV) // 131072000

// Scratch (allocation-free rule -> __device__ globals)
__device__ float g_xh[2u*TT*NB*HH];       // [dir][s][n][j] 16 MB
__device__ float g_z[(size_t)MROWS*2*HH]; // [m][k] tf32-rounded A-matrix, 16 MB
__device__ float g_Wt[(size_t)VV*1024];   // Wout^T [n][k] tf32-rounded, 128 MB
__device__ float g_rowsum[MROWS];         // softmax denominators

// ---------------------------------------------------------------------------
// helpers
// ---------------------------------------------------------------------------
__device__ __forceinline__ unsigned smem_u32(const void* p)
{
    unsigned a;
    asm("{ .reg .u64 t; cvta.to.shared.u64 t, %1; cvt.u32.u64 %0, t; }"
        : "=r"(a) : "l"(p));
    return a;
}

__device__ __forceinline__ uint32_t swz(uint32_t o) { return o ^ ((o >> 3) & 0x70); }

__device__ __forceinline__ float tf32r(float f)      // round-to-nearest tf32
{
    uint32_t r;
    asm("cvt.rna.tf32.f32 %0, %1;" : "=r"(r) : "f"(f));
    return __uint_as_float(r);
}

__device__ __forceinline__ void cp16(uint32_t saddr, const void* gaddr)
{
    asm volatile("cp.async.cg.shared.global [%0], [%1], 16;"
                 :: "r"(saddr), "l"(gaddr) : "memory");
}
__device__ __forceinline__ void cp_commit()
{
    asm volatile("cp.async.commit_group;" ::: "memory");
}
__device__ __forceinline__ void cp_wait1()
{
    asm volatile("cp.async.wait_group 1;" ::: "memory");
}
__device__ __forceinline__ void cp_wait0()
{
    asm volatile("cp.async.wait_group 0;" ::: "memory");
}

__device__ __forceinline__ void ldsm4(uint32_t addr, uint32_t& r0, uint32_t& r1,
                                      uint32_t& r2, uint32_t& r3)
{
    asm volatile("ldmatrix.sync.aligned.m8n8.x4.shared.b16 {%0,%1,%2,%3}, [%4];"
                 : "=r"(r0), "=r"(r1), "=r"(r2), "=r"(r3) : "r"(addr));
}

__device__ __forceinline__ void mma8(float* d, const uint32_t* a,
                                     uint32_t b0, uint32_t b1)
{
    asm volatile("mma.sync.aligned.m16n8k8.row.col.f32.tf32.tf32.f32 "
                 "{%0,%1,%2,%3}, {%4,%5,%6,%7}, {%8,%9}, {%0,%1,%2,%3};"
                 : "+f"(d[0]), "+f"(d[1]), "+f"(d[2]), "+f"(d[3])
                 : "r"(a[0]), "r"(a[1]), "r"(a[2]), "r"(a[3]), "r"(b0), "r"(b1));
}

// ---------------------------------------------------------------------------
// Kernel 1: embedding gather
// ---------------------------------------------------------------------------
__global__ __launch_bounds__(128)
void gather_kernel(const int* __restrict__ x,
                   const float* __restrict__ Ef,
                   const float* __restrict__ Eb)
{
    int b   = blockIdx.x;
    int dir = b >> 12;
    int s   = (b >> 2) & 1023;
    int n   = b & 3;
    int t   = dir ? (TT - 1 - s) : s;
    int tok = x[n * TT + t];
    const float4* src = (const float4*)((dir ? Eb : Ef) + (size_t)tok * HH);
    float4* dst = (float4*)(g_xh + ((size_t)(dir * TT + s) * NB + n) * HH);
    dst[threadIdx.x] = src[threadIdx.x];
}

// ---------------------------------------------------------------------------
// Kernel 1b: transpose Wout[k][n] -> g_Wt[n][k], tf32-rounded at write
// ---------------------------------------------------------------------------
__global__ __launch_bounds__(256)
void transpose_kernel(const float* __restrict__ Wout)
{
    __shared__ float t[32][33];
    int n0 = blockIdx.x * 32;
    int k0 = blockIdx.y * 32;
    int tx = threadIdx.x & 31, ty = threadIdx.x >> 5;
#pragma unroll
    for (int r = 0; r < 32; r += 8)
        t[ty + r][tx] = Wout[(size_t)(k0 + ty + r) * VV + n0 + tx];
    __syncthreads();
#pragma unroll
    for (int r = 0; r < 32; r += 8)
        g_Wt[(size_t)(n0 + ty + r) * 1024 + k0 + tx] = tf32r(t[tx][ty + r]);
}

// ---------------------------------------------------------------------------
// Kernel 1c: zero the softmax row-sum accumulators
// ---------------------------------------------------------------------------
__global__ __launch_bounds__(1024)
void zero_kernel()
{
    g_rowsum[blockIdx.x * 1024 + threadIdx.x] = 0.f;
}

// ---------------------------------------------------------------------------
// Kernel 2: bidirectional RNN scan (cluster-of-8 per direction)
// Phase 1 uses packed fma.rn.f32x2: 4 batch-MACs in 2 FFMA2 per K-element.
// ---------------------------------------------------------------------------
__global__ __cluster_dims__(8, 1, 1) __launch_bounds__(256, 1)
void rnn_kernel(const float* __restrict__ Wh_f, const float* __restrict__ Wh_b,
                const float* __restrict__ bh_f, const float* __restrict__ bh_b,
                float* __restrict__ out)
{
    __shared__ float h_s[2][HH][NB];   // [buf][i][n]
    __shared__ float red[4][64][4];    // [kslice][jj][n]

    int tid = threadIdx.x;
    int jj  = tid & 63;
    int ks  = tid >> 6;
    unsigned crank;
    asm("mov.u32 %0, %%cluster_ctarank;" : "=r"(crank));
    int dir = blockIdx.x >> 3;
    int j   = (int)crank * 64 + jj;

    const float* Wh = dir ? Wh_b : Wh_f;
    const float* bh = dir ? bh_b : bh_f;

    float wreg[128];
#pragma unroll
    for (int u = 0; u < 128; ++u)
        wreg[u] = Wh[(size_t)(ks * 128 + u) * HH + j];
    float bhv = bh[j];

    for (int i = tid; i < HH * NB; i += 256) ((float*)h_s[0])[i] = 0.f;
    __syncthreads();
    asm volatile("barrier.cluster.arrive.aligned;" ::: "memory");
    asm volatile("barrier.cluster.wait.aligned;"   ::: "memory");

    const float* xh_base = g_xh + (size_t)dir * TT * NB * HH;
    uint32_t hbase0 = smem_u32(&h_s[0][ks * 128][0]);
    uint32_t hbase1 = smem_u32(&h_s[1][ks * 128][0]);
    uint32_t redw   = smem_u32(&red[ks][jj][0]);
    int p = 0;

    for (int s = 0; s < TT; ++s) {
        float xv = xh_base[((size_t)s * NB + ks) * HH + j];

        // phase 1: packed partial dot for 4 batch rows over 128 K-elements
        uint64_t a01 = 0ull, a23 = 0ull;
        uint32_t hb = p ? hbase1 : hbase0;
#pragma unroll
        for (int u = 0; u < 128; ++u) {
            uint64_t h01, h23, wd;
            asm("ld.shared.v2.b64 {%0,%1}, [%2];"
                : "=l"(h01), "=l"(h23) : "r"(hb + u * 16));
            uint32_t wu = __float_as_uint(wreg[u]);
            asm("mov.b64 %0, {%1, %1};" : "=l"(wd) : "r"(wu));
            asm("fma.rn.f32x2 %0, %1, %2, %0;" : "+l"(a01) : "l"(h01), "l"(wd));
            asm("fma.rn.f32x2 %0, %1, %2, %0;" : "+l"(a23) : "l"(h23), "l"(wd));
        }
        asm volatile("st.shared.v2.b64 [%0], {%1,%2};"
                     :: "r"(redw), "l"(a01), "l"(a23) : "memory");
        __syncthreads();

        // phase 2: thread = (n = ks, j = jj)
        float v = red[0][jj][ks] + red[1][jj][ks] + red[2][jj][ks] + red[3][jj][ks]
                + xv + bhv;
        float hn = tanhf(v);

        int t_out = dir ? (TT - 1 - s) : s;
        g_z[((size_t)ks * TT + t_out) * (2 * HH) + dir * HH + j] = tf32r(hn);
        if (s == TT - 1)
            out[YSIZE + (size_t)dir * (NB * HH) + ks * HH + j] = hn;

        // broadcast h_new[n=ks][j] into every CTA's h_s[1-p][j][ks]
        unsigned laddr = smem_u32(&h_s[1 - p][j][ks]);
#pragma unroll
        for (int c = 0; c < 8; ++c) {
            unsigned raddr;
            asm volatile("mapa.shared::cluster.u32 %0, %1, %2;"
                         : "=r"(raddr) : "r"(laddr), "r"(c));
            asm volatile("st.shared::cluster.f32 [%0], %1;"
                         :: "r"(raddr), "f"(hn) : "memory");
        }

        asm volatile("barrier.cluster.arrive.aligned;" ::: "memory");
        asm volatile("barrier.cluster.wait.aligned;"   ::: "memory");
        p ^= 1;
    }
}

// ---------------------------------------------------------------------------
// Kernel 3: tf32 mma.sync GEMM,  C = exp(z @ Wt^T + bias), row sums -> g_rowsum
// CTA tile 128x128x32, 8 warps (2m x 4n), 3-stage cp.async pipeline.
// Inputs are pre-rounded tf32 -> no cvt in the mainloop.
// ---------------------------------------------------------------------------
#define GSMEM (3*32768 + 1024)

__global__ __launch_bounds__(256)
void gemm_kernel(const float* __restrict__ bias, float* __restrict__ C)
{
    extern __shared__ char dsm[];
    uint32_t smbase = (smem_u32(dsm) + 1023) & ~1023u;

    int tid  = threadIdx.x;
    int lane = tid & 31, w = tid >> 5;
    int wm = w >> 2, wn = w & 3;
    int m0 = blockIdx.x * 128, n0 = blockIdx.y * 128;

    // ---- loader constants ----
    uint32_t sOff[8];
    const float* gP[8];
#pragma unroll
    for (int q = 0; q < 4; ++q) {
        int idx = q * 256 + tid;
        int row = idx >> 3, c4 = idx & 7;
        sOff[q]     = swz((uint32_t)(row * 128 + c4 * 16));
        sOff[q + 4] = 16384u + sOff[q];
        gP[q]     = g_z  + (size_t)(m0 + row) * 1024 + c4 * 4;
        gP[q + 4] = g_Wt + (size_t)(n0 + row) * 1024 + c4 * 4;
    }

    // ---- fragment address constants ----
    int r = lane & 7, g = lane >> 3;
    uint32_t maskv = (uint32_t)r << 4;
    uint32_t hA = (uint32_t)(g >> 1) << 4;
    uint32_t hB = (uint32_t)(g & 1) << 4;
    uint32_t rowA[4], rowB[2];
#pragma unroll
    for (int mf = 0; mf < 4; ++mf)
        rowA[mf] = (uint32_t)((wm * 64 + mf * 16 + (g & 1) * 8 + r) * 128);
#pragma unroll
    for (int nf2 = 0; nf2 < 2; ++nf2)
        rowB[nf2] = 16384u + (uint32_t)((wn * 32 + nf2 * 16 + (g >> 1) * 8 + r) * 128);

    float acc[4][4][4];
#pragma unroll
    for (int i = 0; i < 4; ++i)
#pragma unroll
        for (int jx = 0; jx < 4; ++jx)
#pragma unroll
            for (int e = 0; e < 4; ++e) acc[i][jx][e] = 0.f;

    // ---- prologue: chunks 0,1 ----
#pragma unroll
    for (int q = 0; q < 8; ++q) cp16(smbase + sOff[q], gP[q]);
    cp_commit();
#pragma unroll
    for (int q = 0; q < 8; ++q) cp16(smbase + 32768 + sOff[q], gP[q] + 32);
    cp_commit();

    for (int c = 0; c < 32; ++c) {
        if (c < 31) cp_wait1(); else cp_wait0();
        __syncthreads();

        if (c + 2 < 32) {
            uint32_t sb = smbase + (uint32_t)((c + 2) % 3) * 32768;
            const int ko = (c + 2) * 32;
#pragma unroll
            for (int q = 0; q < 8; ++q) cp16(sb + sOff[q], gP[q] + ko);
            cp_commit();
        }

        uint32_t sb = smbase + (uint32_t)(c % 3) * 32768;
#pragma unroll
        for (int kk = 0; kk < 4; ++kk) {
            uint32_t kof = (uint32_t)kk << 5;
            uint32_t ua[4][4], ub[2][4];
#pragma unroll
            for (int mf = 0; mf < 4; ++mf)
                ldsm4(sb + rowA[mf] + ((kof + hA) ^ maskv),
                      ua[mf][0], ua[mf][1], ua[mf][2], ua[mf][3]);
#pragma unroll
            for (int nf2 = 0; nf2 < 2; ++nf2)
                ldsm4(sb + rowB[nf2] + ((kof + hB) ^ maskv),
                      ub[nf2][0], ub[nf2][1], ub[nf2][2], ub[nf2][3]);
#pragma unroll
            for (int mf = 0; mf < 4; ++mf)
#pragma unroll
                for (int nf = 0; nf < 4; ++nf)
                    mma8(acc[mf][nf], ua[mf],
                         ub[nf >> 1][(nf & 1) * 2], ub[nf >> 1][(nf & 1) * 2 + 1]);
        }
        __syncthreads();
    }

    // ---- epilogue: exp(logit+bias), store, quad-reduced row sums -> atomic ----
    float bb0[4], bb1[4];
#pragma unroll
    for (int nf = 0; nf < 4; ++nf) {
        int gcol = n0 + wn * 32 + nf * 8 + 2 * (lane & 3);
        bb0[nf] = bias[gcol];
        bb1[nf] = bias[gcol + 1];
    }
#pragma unroll
    for (int mf = 0; mf < 4; ++mf) {
        int grow = m0 + wm * 64 + mf * 16 + (lane >> 2);
        float rsA = 0.f, rsB = 0.f;
#pragma unroll
        for (int nf = 0; nf < 4; ++nf) {
            int gcol = n0 + wn * 32 + nf * 8 + 2 * (lane & 3);
            float e0 = __expf(acc[mf][nf][0] + bb0[nf]);
            float e1 = __expf(acc[mf][nf][1] + bb1[nf]);
            float e2 = __expf(acc[mf][nf][2] + bb0[nf]);
            float e3 = __expf(acc[mf][nf][3] + bb1[nf]);
            *(float2*)(C + (size_t)grow * VV + gcol)       = make_float2(e0, e1);
            *(float2*)(C + (size_t)(grow + 8) * VV + gcol) = make_float2(e2, e3);
            rsA += e0 + e1;
            rsB += e2 + e3;
        }
        // reduce across the 4 lanes of the quad (same row, different columns)
        rsA += __shfl_xor_sync(0xffffffffu, rsA, 1);
        rsA += __shfl_xor_sync(0xffffffffu, rsA, 2);
        rsB += __shfl_xor_sync(0xffffffffu, rsB, 1);
        rsB += __shfl_xor_sync(0xffffffffu, rsB, 2);
        if ((lane & 3) == 0) {
            atomicAdd(&g_rowsum[grow], rsA);
            atomicAdd(&g_rowsum[grow + 8], rsB);
        }
    }
}

// ---------------------------------------------------------------------------
// Kernel 4: normalize pass  C[row][:] *= 1/g_rowsum[row]
// ---------------------------------------------------------------------------
__global__ __launch_bounds__(256, 4)
void norm_kernel(float* __restrict__ C)
{
    float inv = 1.0f / g_rowsum[blockIdx.x];
    float4* x = (float4*)(C + blockIdx.x * (size_t)VV);
    for (int i = threadIdx.x; i < VV / 4; i += 256) {
        float4 v = x[i];
        v.x *= inv; v.y *= inv; v.z *= inv; v.w *= inv;
        x[i] = v;
    }
}

// ---------------------------------------------------------------------------
extern "C" void kernel_launch(void* const* d_in, const int* in_sizes, int n_in,
                              void* d_out, int out_size)
{
    const int*   x       = (const int*)  d_in[0];
    const float* embed_f = (const float*)d_in[1];
    const float* Wh_f    = (const float*)d_in[2];
    const float* bh_f    = (const float*)d_in[3];
    const float* embed_b = (const float*)d_in[4];
    const float* Wh_b    = (const float*)d_in[5];
    const float* bh_b    = (const float*)d_in[6];
    const float* Wout    = (const float*)d_in[7];
    const float* bout    = (const float*)d_in[8];
    float* out = (float*)d_out;

    cudaFuncSetAttribute(gemm_kernel, cudaFuncAttributeMaxDynamicSharedMemorySize,
                         GSMEM);

    gather_kernel<<<2 * TT * NB, 128>>>(x, embed_f, embed_b);
    transpose_kernel<<<dim3(VV / 32, 1024 / 32), 256>>>(Wout);
    zero_kernel<<<MROWS / 1024, 1024>>>();
    rnn_kernel<<<16, 256>>>(Wh_f, Wh_b, bh_f, bh_b, out);
    gemm_kernel<<<dim3(MROWS / 128, VV / 128), 256, GSMEM>>>(bout, out);
    norm_kernel<<<MROWS, 256>>>(out);
}

// round 11
// speedup vs baseline: 5.0933x; 1.7428x over previous
#include <cuda_runtime.h>
#include <cuda_bf16.h>
#include <cstdint>

// Problem constants
#define NB   4
#define TT   1024
#define VV   32000
#define HH   512
#define MROWS (NB*TT)            // 4096
#define YSIZE ((size_t)MROWS*VV) // 131072000

// Scratch (allocation-free rule -> __device__ globals)
__device__ float g_xh[2u*TT*NB*HH];       // [dir][s][n][j] 16 MB
__device__ float g_z[(size_t)MROWS*2*HH]; // [m][k] tf32-rounded A-matrix, 16 MB
__device__ float g_Wt[(size_t)VV*1024];   // Wout^T [n][k] tf32-rounded, 128 MB
__device__ float g_rowsum[MROWS];         // softmax denominators

// ---------------------------------------------------------------------------
// helpers
// ---------------------------------------------------------------------------
__device__ __forceinline__ unsigned smem_u32(const void* p)
{
    unsigned a;
    asm("{ .reg .u64 t; cvta.to.shared.u64 t, %1; cvt.u32.u64 %0, t; }"
        : "=r"(a) : "l"(p));
    return a;
}

__device__ __forceinline__ uint32_t swz(uint32_t o) { return o ^ ((o >> 3) & 0x70); }

__device__ __forceinline__ float tf32r(float f)      // round-to-nearest tf32
{
    uint32_t r;
    asm("cvt.rna.tf32.f32 %0, %1;" : "=r"(r) : "f"(f));
    return __uint_as_float(r);
}

__device__ __forceinline__ void cp16(uint32_t saddr, const void* gaddr)
{
    asm volatile("cp.async.cg.shared.global [%0], [%1], 16;"
                 :: "r"(saddr), "l"(gaddr) : "memory");
}
__device__ __forceinline__ void cp_commit()
{
    asm volatile("cp.async.commit_group;" ::: "memory");
}
__device__ __forceinline__ void cp_wait1()
{
    asm volatile("cp.async.wait_group 1;" ::: "memory");
}
__device__ __forceinline__ void cp_wait0()
{
    asm volatile("cp.async.wait_group 0;" ::: "memory");
}

__device__ __forceinline__ void ldsm4(uint32_t addr, uint32_t& r0, uint32_t& r1,
                                      uint32_t& r2, uint32_t& r3)
{
    asm volatile("ldmatrix.sync.aligned.m8n8.x4.shared.b16 {%0,%1,%2,%3}, [%4];"
                 : "=r"(r0), "=r"(r1), "=r"(r2), "=r"(r3) : "r"(addr));
}

__device__ __forceinline__ void mma8(float* d, const uint32_t* a,
                                     uint32_t b0, uint32_t b1)
{
    asm volatile("mma.sync.aligned.m16n8k8.row.col.f32.tf32.tf32.f32 "
                 "{%0,%1,%2,%3}, {%4,%5,%6,%7}, {%8,%9}, {%0,%1,%2,%3};"
                 : "+f"(d[0]), "+f"(d[1]), "+f"(d[2]), "+f"(d[3])
                 : "r"(a[0]), "r"(a[1]), "r"(a[2]), "r"(a[3]), "r"(b0), "r"(b1));
}

__device__ __forceinline__ void mbar_wait_cluster(uint32_t a, uint32_t ph)
{
    asm volatile("{\n\t.reg .pred P;\n\tWL%=:\n\t"
                 "mbarrier.try_wait.parity.acquire.cluster.shared::cta.b64 P, [%0], %1, 0x989680;\n\t"
                 "@!P bra WL%=;\n\t}"
                 :: "r"(a), "r"(ph) : "memory");
}

// ---------------------------------------------------------------------------
// Kernel 1: embedding gather
// ---------------------------------------------------------------------------
__global__ __launch_bounds__(128)
void gather_kernel(const int* __restrict__ x,
                   const float* __restrict__ Ef,
                   const float* __restrict__ Eb)
{
    int b   = blockIdx.x;
    int dir = b >> 12;
    int s   = (b >> 2) & 1023;
    int n   = b & 3;
    int t   = dir ? (TT - 1 - s) : s;
    int tok = x[n * TT + t];
    const float4* src = (const float4*)((dir ? Eb : Ef) + (size_t)tok * HH);
    float4* dst = (float4*)(g_xh + ((size_t)(dir * TT + s) * NB + n) * HH);
    dst[threadIdx.x] = src[threadIdx.x];
}

// ---------------------------------------------------------------------------
// Kernel 1b: transpose Wout[k][n] -> g_Wt[n][k], tf32-rounded at write
// ---------------------------------------------------------------------------
__global__ __launch_bounds__(256)
void transpose_kernel(const float* __restrict__ Wout)
{
    __shared__ float t[32][33];
    int n0 = blockIdx.x * 32;
    int k0 = blockIdx.y * 32;
    int tx = threadIdx.x & 31, ty = threadIdx.x >> 5;
#pragma unroll
    for (int r = 0; r < 32; r += 8)
        t[ty + r][tx] = Wout[(size_t)(k0 + ty + r) * VV + n0 + tx];
    __syncthreads();
#pragma unroll
    for (int r = 0; r < 32; r += 8)
        g_Wt[(size_t)(n0 + ty + r) * 1024 + k0 + tx] = tf32r(t[tx][ty + r]);
}

// ---------------------------------------------------------------------------
// Kernel 1c: zero the softmax row-sum accumulators
// ---------------------------------------------------------------------------
__global__ __launch_bounds__(1024)
void zero_kernel()
{
    g_rowsum[blockIdx.x * 1024 + threadIdx.x] = 0.f;
}

// ---------------------------------------------------------------------------
// Kernel 2: bidirectional RNN scan, cluster-of-8 per direction.
// Sync via st.async + mbarrier complete_tx (NO per-step cluster barrier).
// Phase 1 (256 thr): packed f32x2 partial dots, K-slice 128, all 4 batches.
// Phase 2 (64 thr): thread jj reduces 4 K-slices for all 4 batches of its
// j-column, tanh, writes g_z, and st.async.v4-broadcasts {h,n=0..3} to all
// 8 CTAs; each 16B tx counts toward the target's mbarrier (8192B/step).
// ---------------------------------------------------------------------------
__global__ __cluster_dims__(8, 1, 1) __launch_bounds__(256, 1)
void rnn_kernel(const float* __restrict__ Wh_f, const float* __restrict__ Wh_b,
                const float* __restrict__ bh_f, const float* __restrict__ bh_b,
                float* __restrict__ out)
{
    __shared__ float    h_s[2][HH][NB];    // [buf][j][n], 16 KB
    __shared__ float    red[2][4][64][4];  // [buf][kslice][jj][n], 8 KB
    __shared__ uint64_t mbar[2];

    int tid = threadIdx.x;
    int jj  = tid & 63;
    int ks  = tid >> 6;
    unsigned crank;
    asm("mov.u32 %0, %%cluster_ctarank;" : "=r"(crank));
    int dir = blockIdx.x >> 3;
    int j   = (int)crank * 64 + jj;

    const float* Wh = dir ? Wh_b : Wh_f;
    const float* bh = dir ? bh_b : bh_f;

    // register-resident weight slice: Wh[ks*128+u][j]
    float wreg[128];
#pragma unroll
    for (int u = 0; u < 128; ++u)
        wreg[u] = Wh[(size_t)(ks * 128 + u) * HH + j];
    float bhv = bh[j];

    // init: zero h buffer 0, init + pre-arm both mbarriers
    for (int i = tid; i < HH * NB; i += 256) ((float*)h_s[0])[i] = 0.f;
    if (tid == 0) {
        uint32_t m0 = smem_u32(&mbar[0]), m1 = smem_u32(&mbar[1]);
        asm volatile("mbarrier.init.shared.b64 [%0], 1;" :: "r"(m0) : "memory");
        asm volatile("mbarrier.init.shared.b64 [%0], 1;" :: "r"(m1) : "memory");
        asm volatile("fence.mbarrier_init.release.cluster;" ::: "memory");
        asm volatile("mbarrier.arrive.expect_tx.shared.b64 _, [%0], %1;"
                     :: "r"(m0), "r"(8192u) : "memory");
        asm volatile("mbarrier.arrive.expect_tx.shared.b64 _, [%0], %1;"
                     :: "r"(m1), "r"(8192u) : "memory");
    }
    __syncthreads();
    asm volatile("barrier.cluster.arrive.aligned;" ::: "memory");
    asm volatile("barrier.cluster.wait.aligned;"   ::: "memory");

    // remote base addresses for all 8 cluster CTAs
    uint32_t hloc = smem_u32(&h_s[0][0][0]);
    uint32_t mloc = smem_u32(&mbar[0]);
    uint32_t rh[8], rm[8];
#pragma unroll
    for (int c = 0; c < 8; ++c) {
        asm("mapa.shared::cluster.u32 %0, %1, %2;" : "=r"(rh[c]) : "r"(hloc), "r"(c));
        asm("mapa.shared::cluster.u32 %0, %1, %2;" : "=r"(rm[c]) : "r"(mloc), "r"(c));
    }

    const float* xh_base = g_xh + (size_t)dir * TT * NB * HH;
    uint32_t ph0 = 0, ph1 = 0;

    for (int s = 0; s < TT; ++s) {
        int rb = s & 1;        // h read buffer / red buffer
        int wb = rb ^ 1;       // h write buffer

        if (s > 0) {
            uint32_t mb = mloc + (uint32_t)rb * 8;
            mbar_wait_cluster(mb, rb ? ph1 : ph0);
            if (tid == 0)
                asm volatile("mbarrier.arrive.expect_tx.shared.b64 _, [%0], %1;"
                             :: "r"(mb), "r"(8192u) : "memory");
            if (rb) ph1 ^= 1; else ph0 ^= 1;
        }

        // prefetch xh for phase 2 (threads 0..63 only)
        float xv0 = 0.f, xv1 = 0.f, xv2 = 0.f, xv3 = 0.f;
        if (tid < 64) {
            const float* xp = xh_base + (size_t)s * NB * HH + j;
            xv0 = xp[0]; xv1 = xp[HH]; xv2 = xp[2 * HH]; xv3 = xp[3 * HH];
        }

        // phase 1: packed partial dot for 4 batch rows over 128 K-elements
        uint64_t a01 = 0ull, a23 = 0ull;
        uint32_t hb = hloc + (uint32_t)rb * (HH * NB * 4) + (uint32_t)(ks * 128) * 16;
#pragma unroll
        for (int u = 0; u < 128; ++u) {
            uint64_t h01, h23, wd;
            asm("ld.shared.v2.b64 {%0,%1}, [%2];"
                : "=l"(h01), "=l"(h23) : "r"(hb + u * 16));
            uint32_t wu = __float_as_uint(wreg[u]);
            asm("mov.b64 %0, {%1, %1};" : "=l"(wd) : "r"(wu));
            asm("fma.rn.f32x2 %0, %1, %2, %0;" : "+l"(a01) : "l"(h01), "l"(wd));
            asm("fma.rn.f32x2 %0, %1, %2, %0;" : "+l"(a23) : "l"(h23), "l"(wd));
        }
        {
            uint32_t rw = smem_u32(&red[rb][ks][jj][0]);
            asm volatile("st.shared.v2.b64 [%0], {%1,%2};"
                         :: "r"(rw), "l"(a01), "l"(a23) : "memory");
        }
        __syncthreads();

        // phase 2: thread jj (tid<64) handles column j, all 4 batches
        if (tid < 64) {
            float4 p0 = *(const float4*)&red[rb][0][jj][0];
            float4 p1 = *(const float4*)&red[rb][1][jj][0];
            float4 p2 = *(const float4*)&red[rb][2][jj][0];
            float4 p3 = *(const float4*)&red[rb][3][jj][0];
            float h0 = tanhf(p0.x + p1.x + p2.x + p3.x + xv0 + bhv);
            float h1 = tanhf(p0.y + p1.y + p2.y + p3.y + xv1 + bhv);
            float h2 = tanhf(p0.z + p1.z + p2.z + p3.z + xv2 + bhv);
            float h3 = tanhf(p0.w + p1.w + p2.w + p3.w + xv3 + bhv);

            int t_out = dir ? (TT - 1 - s) : s;
            size_t zb = (size_t)t_out * (2 * HH) + dir * HH + j;
            g_z[zb]                       = tf32r(h0);
            g_z[zb + (size_t)TT * 2 * HH] = tf32r(h1);
            g_z[zb + (size_t)2 * TT * 2 * HH] = tf32r(h2);
            g_z[zb + (size_t)3 * TT * 2 * HH] = tf32r(h3);
            if (s == TT - 1) {
                size_t ob = YSIZE + (size_t)dir * (NB * HH) + j;
                out[ob]          = h0;
                out[ob + HH]     = h1;
                out[ob + 2 * HH] = h2;
                out[ob + 3 * HH] = h3;
            }

            if (s < TT - 1) {
                uint32_t off = (uint32_t)wb * (HH * NB * 4) + (uint32_t)j * 16;
                uint32_t mof = (uint32_t)wb * 8;
                uint32_t u0 = __float_as_uint(h0), u1 = __float_as_uint(h1);
                uint32_t u2 = __float_as_uint(h2), u3 = __float_as_uint(h3);
#pragma unroll
                for (int c = 0; c < 8; ++c)
                    asm volatile(
                        "st.async.shared::cluster.mbarrier::complete_tx::bytes.v4.b32 "
                        "[%0], {%1,%2,%3,%4}, [%5];"
                        :: "r"(rh[c] + off), "r"(u0), "r"(u1), "r"(u2), "r"(u3),
                           "r"(rm[c] + mof) : "memory");
            }
        }
    }
}

// ---------------------------------------------------------------------------
// Kernel 3: tf32 mma.sync GEMM,  C = exp(z @ Wt^T + bias), row sums -> g_rowsum
// ---------------------------------------------------------------------------
#define GSMEM (3*32768 + 1024)

__global__ __launch_bounds__(256)
void gemm_kernel(const float* __restrict__ bias, float* __restrict__ C)
{
    extern __shared__ char dsm[];
    uint32_t smbase = (smem_u32(dsm) + 1023) & ~1023u;

    int tid  = threadIdx.x;
    int lane = tid & 31, w = tid >> 5;
    int wm = w >> 2, wn = w & 3;
    int m0 = blockIdx.x * 128, n0 = blockIdx.y * 128;

    uint32_t sOff[8];
    const float* gP[8];
#pragma unroll
    for (int q = 0; q < 4; ++q) {
        int idx = q * 256 + tid;
        int row = idx >> 3, c4 = idx & 7;
        sOff[q]     = swz((uint32_t)(row * 128 + c4 * 16));
        sOff[q + 4] = 16384u + sOff[q];
        gP[q]     = g_z  + (size_t)(m0 + row) * 1024 + c4 * 4;
        gP[q + 4] = g_Wt + (size_t)(n0 + row) * 1024 + c4 * 4;
    }

    int r = lane & 7, g = lane >> 3;
    uint32_t maskv = (uint32_t)r << 4;
    uint32_t hA = (uint32_t)(g >> 1) << 4;
    uint32_t hB = (uint32_t)(g & 1) << 4;
    uint32_t rowA[4], rowB[2];
#pragma unroll
    for (int mf = 0; mf < 4; ++mf)
        rowA[mf] = (uint32_t)((wm * 64 + mf * 16 + (g & 1) * 8 + r) * 128);
#pragma unroll
    for (int nf2 = 0; nf2 < 2; ++nf2)
        rowB[nf2] = 16384u + (uint32_t)((wn * 32 + nf2 * 16 + (g >> 1) * 8 + r) * 128);

    float acc[4][4][4];
#pragma unroll
    for (int i = 0; i < 4; ++i)
#pragma unroll
        for (int jx = 0; jx < 4; ++jx)
#pragma unroll
            for (int e = 0; e < 4; ++e) acc[i][jx][e] = 0.f;

#pragma unroll
    for (int q = 0; q < 8; ++q) cp16(smbase + sOff[q], gP[q]);
    cp_commit();
#pragma unroll
    for (int q = 0; q < 8; ++q) cp16(smbase + 32768 + sOff[q], gP[q] + 32);
    cp_commit();

    for (int c = 0; c < 32; ++c) {
        if (c < 31) cp_wait1(); else cp_wait0();
        __syncthreads();

        if (c + 2 < 32) {
            uint32_t sb = smbase + (uint32_t)((c + 2) % 3) * 32768;
            const int ko = (c + 2) * 32;
#pragma unroll
            for (int q = 0; q < 8; ++q) cp16(sb + sOff[q], gP[q] + ko);
            cp_commit();
        }

        uint32_t sb = smbase + (uint32_t)(c % 3) * 32768;
#pragma unroll
        for (int kk = 0; kk < 4; ++kk) {
            uint32_t kof = (uint32_t)kk << 5;
            uint32_t ua[4][4], ub[2][4];
#pragma unroll
            for (int mf = 0; mf < 4; ++mf)
                ldsm4(sb + rowA[mf] + ((kof + hA) ^ maskv),
                      ua[mf][0], ua[mf][1], ua[mf][2], ua[mf][3]);
#pragma unroll
            for (int nf2 = 0; nf2 < 2; ++nf2)
                ldsm4(sb + rowB[nf2] + ((kof + hB) ^ maskv),
                      ub[nf2][0], ub[nf2][1], ub[nf2][2], ub[nf2][3]);
#pragma unroll
            for (int mf = 0; mf < 4; ++mf)
#pragma unroll
                for (int nf = 0; nf < 4; ++nf)
                    mma8(acc[mf][nf], ua[mf],
                         ub[nf >> 1][(nf & 1) * 2], ub[nf >> 1][(nf & 1) * 2 + 1]);
        }
        __syncthreads();
    }

    // epilogue: exp(logit+bias), store, quad-reduced row sums -> atomic
    float bb0[4], bb1[4];
#pragma unroll
    for (int nf = 0; nf < 4; ++nf) {
        int gcol = n0 + wn * 32 + nf * 8 + 2 * (lane & 3);
        bb0[nf] = bias[gcol];
        bb1[nf] = bias[gcol + 1];
    }
#pragma unroll
    for (int mf = 0; mf < 4; ++mf) {
        int grow = m0 + wm * 64 + mf * 16 + (lane >> 2);
        float rsA = 0.f, rsB = 0.f;
#pragma unroll
        for (int nf = 0; nf < 4; ++nf) {
            int gcol = n0 + wn * 32 + nf * 8 + 2 * (lane & 3);
            float e0 = __expf(acc[mf][nf][0] + bb0[nf]);
            float e1 = __expf(acc[mf][nf][1] + bb1[nf]);
            float e2 = __expf(acc[mf][nf][2] + bb0[nf]);
            float e3 = __expf(acc[mf][nf][3] + bb1[nf]);
            *(float2*)(C + (size_t)grow * VV + gcol)       = make_float2(e0, e1);
            *(float2*)(C + (size_t)(grow + 8) * VV + gcol) = make_float2(e2, e3);
            rsA += e0 + e1;
            rsB += e2 + e3;
        }
        rsA += __shfl_xor_sync(0xffffffffu, rsA, 1);
        rsA += __shfl_xor_sync(0xffffffffu, rsA, 2);
        rsB += __shfl_xor_sync(0xffffffffu, rsB, 1);
        rsB += __shfl_xor_sync(0xffffffffu, rsB, 2);
        if ((lane & 3) == 0) {
            atomicAdd(&g_rowsum[grow], rsA);
            atomicAdd(&g_rowsum[grow + 8], rsB);
        }
    }
}

// ---------------------------------------------------------------------------
// Kernel 4: normalize pass  C[row][:] *= 1/g_rowsum[row]
// ---------------------------------------------------------------------------
__global__ __launch_bounds__(256, 4)
void norm_kernel(float* __restrict__ C)
{
    float inv = 1.0f / g_rowsum[blockIdx.x];
    float4* x = (float4*)(C + blockIdx.x * (size_t)VV);
    for (int i = threadIdx.x; i < VV / 4; i += 256) {
        float4 v = x[i];
        v.x *= inv; v.y *= inv; v.z *= inv; v.w *= inv;
        x[i] = v;
    }
}

// ---------------------------------------------------------------------------
extern "C" void kernel_launch(void* const* d_in, const int* in_sizes, int n_in,
                              void* d_out, int out_size)
{
    const int*   x       = (const int*)  d_in[0];
    const float* embed_f = (const float*)d_in[1];
    const float* Wh_f    = (const float*)d_in[2];
    const float* bh_f    = (const float*)d_in[3];
    const float* embed_b = (const float*)d_in[4];
    const float* Wh_b    = (const float*)d_in[5];
    const float* bh_b    = (const float*)d_in[6];
    const float* Wout    = (const float*)d_in[7];
    const float* bout    = (const float*)d_in[8];
    float* out = (float*)d_out;

    cudaFuncSetAttribute(gemm_kernel, cudaFuncAttributeMaxDynamicSharedMemorySize,
                         GSMEM);

    gather_kernel<<<2 * TT * NB, 128>>>(x, embed_f, embed_b);
    transpose_kernel<<<dim3(VV / 32, 1024 / 32), 256>>>(Wout);
    zero_kernel<<<MROWS / 1024, 1024>>>();
    rnn_kernel<<<16, 256>>>(Wh_f, Wh_b, bh_f, bh_b, out);
    gemm_kernel<<<dim3(MROWS / 128, VV / 128), 256, GSMEM>>>(bout, out);
    norm_kernel<<<MROWS, 256>>>(out);
}

// round 12
// speedup vs baseline: 6.0905x; 1.1958x over previous
#include <cuda_runtime.h>
#include <cuda_bf16.h>
#include <cstdint>

// Problem constants
#define NB   4
#define TT   1024
#define VV   32000
#define HH   512
#define MROWS (NB*TT)            // 4096
#define YSIZE ((size_t)MROWS*VV) // 131072000

#define CLU  16                  // cluster size per direction
#define JPC  (HH/CLU)            // 32 j-columns per CTA
#define KSL  8                   // K-slices per CTA
#define ISL  (HH/KSL)            // 64 i-elements per slice

// Scratch (allocation-free rule -> __device__ globals)
__device__ float g_xh[2u*TT*NB*HH];       // [dir][s][n][j] 16 MB
__device__ float g_z[(size_t)MROWS*2*HH]; // [m][k] tf32-rounded A-matrix, 16 MB
__device__ float g_Wt[(size_t)VV*1024];   // Wout^T [n][k] tf32-rounded, 128 MB
__device__ float g_rowsum[MROWS];         // softmax denominators

// ---------------------------------------------------------------------------
// helpers
// ---------------------------------------------------------------------------
__device__ __forceinline__ unsigned smem_u32(const void* p)
{
    unsigned a;
    asm("{ .reg .u64 t; cvta.to.shared.u64 t, %1; cvt.u32.u64 %0, t; }"
        : "=r"(a) : "l"(p));
    return a;
}

__device__ __forceinline__ uint32_t swz(uint32_t o) { return o ^ ((o >> 3) & 0x70); }

__device__ __forceinline__ float tf32r(float f)      // round-to-nearest tf32
{
    uint32_t r;
    asm("cvt.rna.tf32.f32 %0, %1;" : "=r"(r) : "f"(f));
    return __uint_as_float(r);
}

__device__ __forceinline__ void cp16(uint32_t saddr, const void* gaddr)
{
    asm volatile("cp.async.cg.shared.global [%0], [%1], 16;"
                 :: "r"(saddr), "l"(gaddr) : "memory");
}
__device__ __forceinline__ void cp_commit()
{
    asm volatile("cp.async.commit_group;" ::: "memory");
}
__device__ __forceinline__ void cp_wait1()
{
    asm volatile("cp.async.wait_group 1;" ::: "memory");
}
__device__ __forceinline__ void cp_wait0()
{
    asm volatile("cp.async.wait_group 0;" ::: "memory");
}

__device__ __forceinline__ void ldsm4(uint32_t addr, uint32_t& r0, uint32_t& r1,
                                      uint32_t& r2, uint32_t& r3)
{
    asm volatile("ldmatrix.sync.aligned.m8n8.x4.shared.b16 {%0,%1,%2,%3}, [%4];"
                 : "=r"(r0), "=r"(r1), "=r"(r2), "=r"(r3) : "r"(addr));
}

__device__ __forceinline__ void mma8(float* d, const uint32_t* a,
                                     uint32_t b0, uint32_t b1)
{
    asm volatile("mma.sync.aligned.m16n8k8.row.col.f32.tf32.tf32.f32 "
                 "{%0,%1,%2,%3}, {%4,%5,%6,%7}, {%8,%9}, {%0,%1,%2,%3};"
                 : "+f"(d[0]), "+f"(d[1]), "+f"(d[2]), "+f"(d[3])
                 : "r"(a[0]), "r"(a[1]), "r"(a[2]), "r"(a[3]), "r"(b0), "r"(b1));
}

__device__ __forceinline__ void mbar_wait_cluster(uint32_t a, uint32_t ph)
{
    asm volatile("{\n\t.reg .pred P;\n\tWL%=:\n\t"
                 "mbarrier.try_wait.parity.acquire.cluster.shared::cta.b64 P, [%0], %1, 0x989680;\n\t"
                 "@!P bra WL%=;\n\t}"
                 :: "r"(a), "r"(ph) : "memory");
}

// ---------------------------------------------------------------------------
// Kernel 1: embedding gather
// ---------------------------------------------------------------------------
__global__ __launch_bounds__(128)
void gather_kernel(const int* __restrict__ x,
                   const float* __restrict__ Ef,
                   const float* __restrict__ Eb)
{
    int b   = blockIdx.x;
    int dir = b >> 12;
    int s   = (b >> 2) & 1023;
    int n   = b & 3;
    int t   = dir ? (TT - 1 - s) : s;
    int tok = x[n * TT + t];
    const float4* src = (const float4*)((dir ? Eb : Ef) + (size_t)tok * HH);
    float4* dst = (float4*)(g_xh + ((size_t)(dir * TT + s) * NB + n) * HH);
    dst[threadIdx.x] = src[threadIdx.x];
}

// ---------------------------------------------------------------------------
// Kernel 1b: transpose Wout[k][n] -> g_Wt[n][k], tf32-rounded at write
// ---------------------------------------------------------------------------
__global__ __launch_bounds__(256)
void transpose_kernel(const float* __restrict__ Wout)
{
    __shared__ float t[32][33];
    int n0 = blockIdx.x * 32;
    int k0 = blockIdx.y * 32;
    int tx = threadIdx.x & 31, ty = threadIdx.x >> 5;
#pragma unroll
    for (int r = 0; r < 32; r += 8)
        t[ty + r][tx] = Wout[(size_t)(k0 + ty + r) * VV + n0 + tx];
    __syncthreads();
#pragma unroll
    for (int r = 0; r < 32; r += 8)
        g_Wt[(size_t)(n0 + ty + r) * 1024 + k0 + tx] = tf32r(t[tx][ty + r]);
}

// ---------------------------------------------------------------------------
// Kernel 1c: zero the softmax row-sum accumulators
// ---------------------------------------------------------------------------
__global__ __launch_bounds__(1024)
void zero_kernel()
{
    g_rowsum[blockIdx.x * 1024 + threadIdx.x] = 0.f;
}

// ---------------------------------------------------------------------------
// Kernel 2: bidirectional RNN scan, cluster-of-16 per direction.
// Sync via st.async + mbarrier complete_tx (no per-step cluster barrier).
// Thread (ks=tid>>5, jj=tid&31): K-slice ks (64 i-elems) of column j=crank*32+jj.
// Phase 2 (32 thr): reduce 8 K-slices x 4 batches, tanh, st.async.v4 broadcast
// to all 16 CTAs (each 16B tx counts toward target's mbarrier; 8192B/step).
// ---------------------------------------------------------------------------
__global__ __cluster_dims__(CLU, 1, 1) __launch_bounds__(256, 1)
void rnn_kernel(const float* __restrict__ Wh_f, const float* __restrict__ Wh_b,
                const float* __restrict__ bh_f, const float* __restrict__ bh_b,
                float* __restrict__ out)
{
    __shared__ float    h_s[2][HH][NB];       // [buf][j][n], 16 KB
    __shared__ float    red[2][KSL][JPC][4];  // [buf][kslice][jj][n], 8 KB
    __shared__ uint64_t mbar[2];

    int tid = threadIdx.x;
    int jj  = tid & 31;
    int ks  = tid >> 5;            // 0..7
    unsigned crank;
    asm("mov.u32 %0, %%cluster_ctarank;" : "=r"(crank));
    int dir = blockIdx.x >> 4;
    int j   = (int)crank * JPC + jj;

    const float* Wh = dir ? Wh_b : Wh_f;
    const float* bh = dir ? bh_b : bh_f;

    // register-resident weight slice: Wh[ks*64+u][j]
    float wreg[ISL];
#pragma unroll
    for (int u = 0; u < ISL; ++u)
        wreg[u] = Wh[(size_t)(ks * ISL + u) * HH + j];
    float bhv = bh[j];

    // init: zero h buffer 0, init + pre-arm both mbarriers
    for (int i = tid; i < HH * NB; i += 256) ((float*)h_s[0])[i] = 0.f;
    if (tid == 0) {
        uint32_t m0 = smem_u32(&mbar[0]), m1 = smem_u32(&mbar[1]);
        asm volatile("mbarrier.init.shared.b64 [%0], 1;" :: "r"(m0) : "memory");
        asm volatile("mbarrier.init.shared.b64 [%0], 1;" :: "r"(m1) : "memory");
        asm volatile("fence.mbarrier_init.release.cluster;" ::: "memory");
        asm volatile("mbarrier.arrive.expect_tx.shared.b64 _, [%0], %1;"
                     :: "r"(m0), "r"(8192u) : "memory");
        asm volatile("mbarrier.arrive.expect_tx.shared.b64 _, [%0], %1;"
                     :: "r"(m1), "r"(8192u) : "memory");
    }
    __syncthreads();
    asm volatile("barrier.cluster.arrive.aligned;" ::: "memory");
    asm volatile("barrier.cluster.wait.aligned;"   ::: "memory");

    // remote base addresses for all 16 cluster CTAs
    uint32_t hloc = smem_u32(&h_s[0][0][0]);
    uint32_t mloc = smem_u32(&mbar[0]);
    uint32_t rh[CLU], rm[CLU];
#pragma unroll
    for (int c = 0; c < CLU; ++c) {
        asm("mapa.shared::cluster.u32 %0, %1, %2;" : "=r"(rh[c]) : "r"(hloc), "r"(c));
        asm("mapa.shared::cluster.u32 %0, %1, %2;" : "=r"(rm[c]) : "r"(mloc), "r"(c));
    }

    const float* xh_base = g_xh + (size_t)dir * TT * NB * HH;
    uint32_t ph0 = 0, ph1 = 0;

    for (int s = 0; s < TT; ++s) {
        int rb = s & 1;        // h read buffer / red buffer
        int wb = rb ^ 1;       // h write buffer

        if (s > 0) {
            uint32_t mb = mloc + (uint32_t)rb * 8;
            mbar_wait_cluster(mb, rb ? ph1 : ph0);
            if (tid == 0)
                asm volatile("mbarrier.arrive.expect_tx.shared.b64 _, [%0], %1;"
                             :: "r"(mb), "r"(8192u) : "memory");
            if (rb) ph1 ^= 1; else ph0 ^= 1;
        }

        // prefetch xh for phase 2 (threads 0..31 only)
        float xv0 = 0.f, xv1 = 0.f, xv2 = 0.f, xv3 = 0.f;
        if (tid < JPC) {
            const float* xp = xh_base + (size_t)s * NB * HH + j;
            xv0 = xp[0]; xv1 = xp[HH]; xv2 = xp[2 * HH]; xv3 = xp[3 * HH];
        }

        // phase 1: packed partial dot for 4 batch rows over 64 K-elements
        uint64_t a01 = 0ull, a23 = 0ull;
        uint32_t hb = hloc + (uint32_t)rb * (HH * NB * 4) + (uint32_t)(ks * ISL) * 16;
#pragma unroll
        for (int u = 0; u < ISL; ++u) {
            uint64_t h01, h23, wd;
            asm("ld.shared.v2.b64 {%0,%1}, [%2];"
                : "=l"(h01), "=l"(h23) : "r"(hb + u * 16));
            uint32_t wu = __float_as_uint(wreg[u]);
            asm("mov.b64 %0, {%1, %1};" : "=l"(wd) : "r"(wu));
            asm("fma.rn.f32x2 %0, %1, %2, %0;" : "+l"(a01) : "l"(h01), "l"(wd));
            asm("fma.rn.f32x2 %0, %1, %2, %0;" : "+l"(a23) : "l"(h23), "l"(wd));
        }
        {
            uint32_t rw = smem_u32(&red[rb][ks][jj][0]);
            asm volatile("st.shared.v2.b64 [%0], {%1,%2};"
                         :: "r"(rw), "l"(a01), "l"(a23) : "memory");
        }
        __syncthreads();

        // phase 2: thread jj (tid<32) handles column j, all 4 batches
        if (tid < JPC) {
            float4 p0 = *(const float4*)&red[rb][0][jj][0];
            float4 p1 = *(const float4*)&red[rb][1][jj][0];
            float4 p2 = *(const float4*)&red[rb][2][jj][0];
            float4 p3 = *(const float4*)&red[rb][3][jj][0];
            float4 p4 = *(const float4*)&red[rb][4][jj][0];
            float4 p5 = *(const float4*)&red[rb][5][jj][0];
            float4 p6 = *(const float4*)&red[rb][6][jj][0];
            float4 p7 = *(const float4*)&red[rb][7][jj][0];
            float h0 = tanhf(((p0.x + p1.x) + (p2.x + p3.x)) +
                             ((p4.x + p5.x) + (p6.x + p7.x)) + xv0 + bhv);
            float h1 = tanhf(((p0.y + p1.y) + (p2.y + p3.y)) +
                             ((p4.y + p5.y) + (p6.y + p7.y)) + xv1 + bhv);
            float h2 = tanhf(((p0.z + p1.z) + (p2.z + p3.z)) +
                             ((p4.z + p5.z) + (p6.z + p7.z)) + xv2 + bhv);
            float h3 = tanhf(((p0.w + p1.w) + (p2.w + p3.w)) +
                             ((p4.w + p5.w) + (p6.w + p7.w)) + xv3 + bhv);

            int t_out = dir ? (TT - 1 - s) : s;
            size_t zb = (size_t)t_out * (2 * HH) + dir * HH + j;
            g_z[zb]                           = tf32r(h0);
            g_z[zb + (size_t)TT * 2 * HH]     = tf32r(h1);
            g_z[zb + (size_t)2 * TT * 2 * HH] = tf32r(h2);
            g_z[zb + (size_t)3 * TT * 2 * HH] = tf32r(h3);
            if (s == TT - 1) {
                size_t ob = YSIZE + (size_t)dir * (NB * HH) + j;
                out[ob]          = h0;
                out[ob + HH]     = h1;
                out[ob + 2 * HH] = h2;
                out[ob + 3 * HH] = h3;
            }

            if (s < TT - 1) {
                uint32_t off = (uint32_t)wb * (HH * NB * 4) + (uint32_t)j * 16;
                uint32_t mof = (uint32_t)wb * 8;
                uint32_t u0 = __float_as_uint(h0), u1 = __float_as_uint(h1);
                uint32_t u2 = __float_as_uint(h2), u3 = __float_as_uint(h3);
#pragma unroll
                for (int c = 0; c < CLU; ++c)
                    asm volatile(
                        "st.async.shared::cluster.mbarrier::complete_tx::bytes.v4.b32 "
                        "[%0], {%1,%2,%3,%4}, [%5];"
                        :: "r"(rh[c] + off), "r"(u0), "r"(u1), "r"(u2), "r"(u3),
                           "r"(rm[c] + mof) : "memory");
            }
        }
    }
}

// ---------------------------------------------------------------------------
// Kernel 3: tf32 mma.sync GEMM,  C = exp(z @ Wt^T + bias), row sums -> g_rowsum
// ---------------------------------------------------------------------------
#define GSMEM (3*32768 + 1024)

__global__ __launch_bounds__(256)
void gemm_kernel(const float* __restrict__ bias, float* __restrict__ C)
{
    extern __shared__ char dsm[];
    uint32_t smbase = (smem_u32(dsm) + 1023) & ~1023u;

    int tid  = threadIdx.x;
    int lane = tid & 31, w = tid >> 5;
    int wm = w >> 2, wn = w & 3;
    int m0 = blockIdx.x * 128, n0 = blockIdx.y * 128;

    uint32_t sOff[8];
    const float* gP[8];
#pragma unroll
    for (int q = 0; q < 4; ++q) {
        int idx = q * 256 + tid;
        int row = idx >> 3, c4 = idx & 7;
        sOff[q]     = swz((uint32_t)(row * 128 + c4 * 16));
        sOff[q + 4] = 16384u + sOff[q];
        gP[q]     = g_z  + (size_t)(m0 + row) * 1024 + c4 * 4;
        gP[q + 4] = g_Wt + (size_t)(n0 + row) * 1024 + c4 * 4;
    }

    int r = lane & 7, g = lane >> 3;
    uint32_t maskv = (uint32_t)r << 4;
    uint32_t hA = (uint32_t)(g >> 1) << 4;
    uint32_t hB = (uint32_t)(g & 1) << 4;
    uint32_t rowA[4], rowB[2];
#pragma unroll
    for (int mf = 0; mf < 4; ++mf)
        rowA[mf] = (uint32_t)((wm * 64 + mf * 16 + (g & 1) * 8 + r) * 128);
#pragma unroll
    for (int nf2 = 0; nf2 < 2; ++nf2)
        rowB[nf2] = 16384u + (uint32_t)((wn * 32 + nf2 * 16 + (g >> 1) * 8 + r) * 128);

    float acc[4][4][4];
#pragma unroll
    for (int i = 0; i < 4; ++i)
#pragma unroll
        for (int jx = 0; jx < 4; ++jx)
#pragma unroll
            for (int e = 0; e < 4; ++e) acc[i][jx][e] = 0.f;

#pragma unroll
    for (int q = 0; q < 8; ++q) cp16(smbase + sOff[q], gP[q]);
    cp_commit();
#pragma unroll
    for (int q = 0; q < 8; ++q) cp16(smbase + 32768 + sOff[q], gP[q] + 32);
    cp_commit();

    for (int c = 0; c < 32; ++c) {
        if (c < 31) cp_wait1(); else cp_wait0();
        __syncthreads();

        if (c + 2 < 32) {
            uint32_t sb = smbase + (uint32_t)((c + 2) % 3) * 32768;
            const int ko = (c + 2) * 32;
#pragma unroll
            for (int q = 0; q < 8; ++q) cp16(sb + sOff[q], gP[q] + ko);
            cp_commit();
        }

        uint32_t sb = smbase + (uint32_t)(c % 3) * 32768;
#pragma unroll
        for (int kk = 0; kk < 4; ++kk) {
            uint32_t kof = (uint32_t)kk << 5;
            uint32_t ua[4][4], ub[2][4];
#pragma unroll
            for (int mf = 0; mf < 4; ++mf)
                ldsm4(sb + rowA[mf] + ((kof + hA) ^ maskv),
                      ua[mf][0], ua[mf][1], ua[mf][2], ua[mf][3]);
#pragma unroll
            for (int nf2 = 0; nf2 < 2; ++nf2)
                ldsm4(sb + rowB[nf2] + ((kof + hB) ^ maskv),
                      ub[nf2][0], ub[nf2][1], ub[nf2][2], ub[nf2][3]);
#pragma unroll
            for (int mf = 0; mf < 4; ++mf)
#pragma unroll
                for (int nf = 0; nf < 4; ++nf)
                    mma8(acc[mf][nf], ua[mf],
                         ub[nf >> 1][(nf & 1) * 2], ub[nf >> 1][(nf & 1) * 2 + 1]);
        }
        __syncthreads();
    }

    // epilogue: exp(logit+bias), store, quad-reduced row sums -> atomic
    float bb0[4], bb1[4];
#pragma unroll
    for (int nf = 0; nf < 4; ++nf) {
        int gcol = n0 + wn * 32 + nf * 8 + 2 * (lane & 3);
        bb0[nf] = bias[gcol];
        bb1[nf] = bias[gcol + 1];
    }
#pragma unroll
    for (int mf = 0; mf < 4; ++mf) {
        int grow = m0 + wm * 64 + mf * 16 + (lane >> 2);
        float rsA = 0.f, rsB = 0.f;
#pragma unroll
        for (int nf = 0; nf < 4; ++nf) {
            int gcol = n0 + wn * 32 + nf * 8 + 2 * (lane & 3);
            float e0 = __expf(acc[mf][nf][0] + bb0[nf]);
            float e1 = __expf(acc[mf][nf][1] + bb1[nf]);
            float e2 = __expf(acc[mf][nf][2] + bb0[nf]);
            float e3 = __expf(acc[mf][nf][3] + bb1[nf]);
            *(float2*)(C + (size_t)grow * VV + gcol)       = make_float2(e0, e1);
            *(float2*)(C + (size_t)(grow + 8) * VV + gcol) = make_float2(e2, e3);
            rsA += e0 + e1;
            rsB += e2 + e3;
        }
        rsA += __shfl_xor_sync(0xffffffffu, rsA, 1);
        rsA += __shfl_xor_sync(0xffffffffu, rsA, 2);
        rsB += __shfl_xor_sync(0xffffffffu, rsB, 1);
        rsB += __shfl_xor_sync(0xffffffffu, rsB, 2);
        if ((lane & 3) == 0) {
            atomicAdd(&g_rowsum[grow], rsA);
            atomicAdd(&g_rowsum[grow + 8], rsB);
        }
    }
}

// ---------------------------------------------------------------------------
// Kernel 4: normalize pass  C[row][:] *= 1/g_rowsum[row]
// ---------------------------------------------------------------------------
__global__ __launch_bounds__(256, 4)
void norm_kernel(float* __restrict__ C)
{
    float inv = 1.0f / g_rowsum[blockIdx.x];
    float4* x = (float4*)(C + blockIdx.x * (size_t)VV);
    for (int i = threadIdx.x; i < VV / 4; i += 256) {
        float4 v = x[i];
        v.x *= inv; v.y *= inv; v.z *= inv; v.w *= inv;
        x[i] = v;
    }
}

// ---------------------------------------------------------------------------
extern "C" void kernel_launch(void* const* d_in, const int* in_sizes, int n_in,
                              void* d_out, int out_size)
{
    const int*   x       = (const int*)  d_in[0];
    const float* embed_f = (const float*)d_in[1];
    const float* Wh_f    = (const float*)d_in[2];
    const float* bh_f    = (const float*)d_in[3];
    const float* embed_b = (const float*)d_in[4];
    const float* Wh_b    = (const float*)d_in[5];
    const float* bh_b    = (const float*)d_in[6];
    const float* Wout    = (const float*)d_in[7];
    const float* bout    = (const float*)d_in[8];
    float* out = (float*)d_out;

    cudaFuncSetAttribute(gemm_kernel, cudaFuncAttributeMaxDynamicSharedMemorySize,
                         GSMEM);
    cudaFuncSetAttribute(rnn_kernel,
                         cudaFuncAttributeNonPortableClusterSizeAllowed, 1);

    gather_kernel<<<2 * TT * NB, 128>>>(x, embed_f, embed_b);
    transpose_kernel<<<dim3(VV / 32, 1024 / 32), 256>>>(Wout);
    zero_kernel<<<MROWS / 1024, 1024>>>();
    rnn_kernel<<<2 * CLU, 256>>>(Wh_f, Wh_b, bh_f, bh_b, out);
    gemm_kernel<<<dim3(MROWS / 128, VV / 128), 256, GSMEM>>>(bout, out);
    norm_kernel<<<MROWS, 256>>>(out);
}